// round 6
// baseline (speedup 1.0000x reference)
#include <cuda_runtime.h>
#include <cuda_fp16.h>
#include <cstdint>

#define NTOT   262144
#define NTILES 8192                     // NTOT / 32 n per tile
#define SCALE  0.14433756729740643f     // 1/sqrt(48)

// ---- smem layout (bytes, from 1KB-aligned base) ----
// A: 128 rows x 136 fp16 (pitch 272B). k: [0..54]=xh, 55=0, [56..110]=xl, 111..135=0
#define OFF_A   0
// B: 112 rows(j) x 184 fp16 (pitch 368B). k: [0..55]=wh, [56..111]=wh, [112..167]=wl, 168+=0
#define OFF_B   34816
// XP: x fp32 copy, 128 rows x 60 f32 (pitch 240B), pads zero
#define OFF_XP  76032
// DS: D staging, 128 rows x 116 f32 (pitch 464B)
#define OFF_DS  106752
// OS: out staging, 32 n x 224 f32
#define OFF_OS  166144
// AT: attn, 32 n x 4 s x float4
#define OFF_AT  194816
// SB: bias, 64 f32 (55 real + zeros)
#define OFF_SB  196864
#define SMEM_USED 197120
#define SMEM_TOTAL (SMEM_USED + 1024)

// precomputed folded B in fp16 (same layout as smem B)
__device__ unsigned short g_B[112 * 184];

// ============ prep: fold weights, fp16 hi/lo split ============
__global__ void prep_kernel(const float* __restrict__ wq, const float* __restrict__ wk,
                            const float* __restrict__ wv, const float* __restrict__ wfc) {
    int idx = blockIdx.x * blockDim.x + threadIdx.x;
    if (idx >= 112 * 184) return;
    int j = idx / 184;
    int k = idx - j * 184;
    int sec = (k < 56) ? 0 : (k < 112) ? 1 : (k < 168) ? 2 : 3;
    float w = 0.f;
    if (sec < 3) {
        int d = k - sec * 56;
        if (d < 55) {
            if (j < 55) {                         // M[d][j] = SCALE * wq(:,d).wk(:,j)
                float s = 0.f;
                #pragma unroll 8
                for (int e = 0; e < 48; e++) s += wq[e * 55 + d] * wk[e * 55 + j];
                w = s * SCALE;
            } else if (j >= 56 && j < 111) {      // G[d][dd] = wv(:,d).wfc(dd,:)
                int dd = j - 56;
                float s = 0.f;
                #pragma unroll 8
                for (int e = 0; e < 48; e++) s += wv[e * 55 + d] * wfc[dd * 48 + e];
                w = s;
            }
        }
    }
    __half wh = __float2half_rn(w);
    __half o;
    if (sec == 2)      o = __float2half_rn(w - __half2float(wh));   // wl
    else if (sec == 3) o = __float2half_rn(0.f);
    else               o = wh;
    g_B[idx] = __half_as_ushort(o);
}

// ============ PTX helpers (baseline ISA only) ============
__device__ __forceinline__ uint32_t s2u(const void* p) {
    uint32_t a;
    asm("{ .reg .u64 t; cvta.to.shared.u64 t, %1; cvt.u32.u64 %0, t; }" : "=r"(a) : "l"(p));
    return a;
}
__device__ __forceinline__ void ldsm4(uint32_t* r, uint32_t addr) {
    asm volatile("ldmatrix.sync.aligned.m8n8.x4.shared.b16 {%0,%1,%2,%3}, [%4];"
                 : "=r"(r[0]), "=r"(r[1]), "=r"(r[2]), "=r"(r[3]) : "r"(addr));
}
__device__ __forceinline__ void mma16816(float* c, const uint32_t* a, uint32_t b0, uint32_t b1) {
    asm volatile("mma.sync.aligned.m16n8k16.row.col.f32.f16.f16.f32 "
                 "{%0,%1,%2,%3}, {%4,%5,%6,%7}, {%8,%9}, {%0,%1,%2,%3};"
                 : "+f"(c[0]), "+f"(c[1]), "+f"(c[2]), "+f"(c[3])
                 : "r"(a[0]), "r"(a[1]), "r"(a[2]), "r"(a[3]), "r"(b0), "r"(b1));
}

// ============ main kernel ============
__global__ __launch_bounds__(256) void mha_kernel(const float* __restrict__ x,
                                                  const float* __restrict__ bfc,
                                                  float* __restrict__ out) {
    extern __shared__ char smraw[];
    uint32_t sb0 = s2u(smraw);
    uint32_t sb  = (sb0 + 1023u) & ~1023u;
    char* sm = smraw + (sb - sb0);

    const int tid  = threadIdx.x;
    const int wid  = tid >> 5;
    const int lane = tid & 31;

    // ---- one-time init ----
    for (int i = tid; i < 112 * 184; i += 256)
        ((unsigned short*)(sm + OFF_B))[i] = g_B[i];
    for (int i = tid; i < 34816 / 4; i += 256)           // zero A (pads persist)
        *(uint32_t*)(sm + OFF_A + i * 4) = 0u;
    for (int i = tid; i < 30720 / 4; i += 256)           // zero XP (pads persist)
        *(float*)(sm + OFF_XP + i * 4) = 0.f;
    for (int i = tid; i < 64; i += 256)
        *(float*)(sm + OFF_SB + i * 4) = (i < 55) ? bfc[i] : 0.f;
    __syncthreads();

    // ldmatrix per-lane address components
    const int R0 = wid * 16;
    const uint32_t aAddrBase = sb + OFF_A + (uint32_t)(R0 + (lane & 15)) * 272
                             + (uint32_t)((lane >> 4) & 1) * 16;
    const int jb   = (lane & 7) + ((lane >> 4) & 1) * 8;
    const int kadd = ((lane >> 3) & 1) * 16;

    float* DS = (float*)(sm + OFF_DS);
    const float* XP = (const float*)(sm + OFF_XP);
    const float* SB = (const float*)(sm + OFF_SB);

    for (int t = blockIdx.x; t < NTILES; t += gridDim.x) {
        // ======== Stage A: load x tile, fp16 split, scatter ========
        {
            const float4* xin = (const float4*)(x + (size_t)t * 7040);
            #pragma unroll
            for (int i = 0; i < 7; i++) {
                int idx = tid + 256 * i;
                if (idx < 1760) {
                    float4 v = xin[idx];
                    float vv[4] = {v.x, v.y, v.z, v.w};
                    int n_l = idx / 55;
                    int l0  = (idx - n_l * 55) * 4;
                    #pragma unroll
                    for (int jj = 0; jj < 4; jj++) {
                        int l  = l0 + jj;
                        int r  = l / 10, cc = l - r * 10;
                        int p1 = r / 11, h = r - p1 * 11;
                        int p2 = cc / 5, w = cc - p2 * 5;
                        int row = n_l * 4 + p1 * 2 + p2;
                        int d   = h * 5 + w;
                        float val = vv[jj];
                        *(float*)(sm + OFF_XP + (row * 60 + d) * 4) = val;
                        __half hh = __float2half_rn(val);
                        __half hl = __float2half_rn(val - __half2float(hh));
                        *(__half*)(sm + OFF_A + row * 272 + d * 2)        = hh;
                        *(__half*)(sm + OFF_A + row * 272 + (56 + d) * 2) = hl;
                    }
                }
            }
        }
        __syncthreads();

        // ======== Stage B: MMA (14 n-tiles as 7 pairs, 7+4 k-steps), stage D ========
        {
            uint32_t aF[7][4];
            #pragma unroll
            for (int ks = 0; ks < 7; ks++) ldsm4(aF[ks], aAddrBase + ks * 32);

            const int gid = lane >> 2, tig = lane & 3;
            #pragma unroll
            for (int ntp = 0; ntp < 7; ntp++) {
                float acc0[4] = {0.f, 0.f, 0.f, 0.f};
                float acc1[4] = {0.f, 0.f, 0.f, 0.f};
                uint32_t bbase = sb + OFF_B + (uint32_t)(ntp * 16 + jb) * 368 + kadd;
                #pragma unroll
                for (int ks = 0; ks < 7; ks++) {           // A[xh|xl] x B[wh|wh]
                    uint32_t bf[4];
                    ldsm4(bf, bbase + ks * 32);
                    mma16816(acc0, aF[ks], bf[0], bf[1]);
                    mma16816(acc1, aF[ks], bf[2], bf[3]);
                }
                #pragma unroll
                for (int ks = 0; ks < 4; ks++) {           // A[xh(+xl x 0)] x B[wl|0]
                    uint32_t bf[4];
                    ldsm4(bf, bbase + 224 + ks * 32);
                    mma16816(acc0, aF[ks], bf[0], bf[1]);
                    mma16816(acc1, aF[ks], bf[2], bf[3]);
                }
                int row = R0 + gid;
                int c0  = ntp * 16 + 2 * tig;
                *(float2*)(DS + row * 116 + c0)           = make_float2(acc0[0], acc0[1]);
                *(float2*)(DS + (row + 8) * 116 + c0)     = make_float2(acc0[2], acc0[3]);
                *(float2*)(DS + row * 116 + c0 + 8)       = make_float2(acc1[0], acc1[1]);
                *(float2*)(DS + (row + 8) * 116 + c0 + 8) = make_float2(acc1[2], acc1[3]);
            }
        }
        __syncthreads();

        // ======== Stage C: S = T x^T, softmax (all 8 warps) ========
        {
            int nl = tid >> 3;
            int s4 = (tid >> 1) & 3;
            int tp = tid & 1;
            const float4* tr = (const float4*)(DS + (nl * 4 + s4) * 116);
            const float4* x0 = (const float4*)(XP + (nl * 4 + 2 * tp) * 60);
            const float4* x1 = (const float4*)(XP + (nl * 4 + 2 * tp + 1) * 60);
            float sv0 = 0.f, sv1 = 0.f;
            #pragma unroll
            for (int i = 0; i < 14; i++) {
                float4 tv = tr[i], a = x0[i], b = x1[i];
                sv0 += tv.x * a.x + tv.y * a.y + tv.z * a.z + tv.w * a.w;
                sv1 += tv.x * b.x + tv.y * b.y + tv.z * b.z + tv.w * b.w;
            }
            float o0 = __shfl_xor_sync(0xffffffffu, sv0, 1);
            float o1 = __shfl_xor_sync(0xffffffffu, sv1, 1);
            float t0, t1, t2, t3;
            if (tp == 0) { t0 = sv0; t1 = sv1; t2 = o0; t3 = o1; }
            else         { t0 = o0;  t1 = o1;  t2 = sv0; t3 = sv1; }
            float m = fmaxf(fmaxf(t0, t1), fmaxf(t2, t3));
            float e0 = __expf(t0 - m), e1 = __expf(t1 - m);
            float e2 = __expf(t2 - m), e3 = __expf(t3 - m);
            float inv = 1.f / (e0 + e1 + e2 + e3);
            if (tp == 0)
                *(float4*)(sm + OFF_AT + (nl * 4 + s4) * 16) =
                    make_float4(e0 * inv, e1 * inv, e2 * inv, e3 * inv);
        }
        __syncthreads();

        // ======== Stage D: out = b + attn * U, stage patch-linear ========
        {
            int nl = tid >> 3;
            int s4 = (tid >> 1) & 3;
            int dh = tid & 1;
            int d0 = dh * 28;
            float4 at = *(const float4*)(sm + OFF_AT + (nl * 4 + s4) * 16);
            float av[4] = {at.x, at.y, at.z, at.w};
            float acc[28];
            {
                const float4* bb = (const float4*)(SB + d0);
                #pragma unroll
                for (int i = 0; i < 7; i++) {
                    float4 b = bb[i];
                    acc[4*i] = b.x; acc[4*i+1] = b.y; acc[4*i+2] = b.z; acc[4*i+3] = b.w;
                }
            }
            #pragma unroll
            for (int tt = 0; tt < 4; tt++) {
                const float4* ur = (const float4*)(DS + (nl * 4 + tt) * 116 + 56 + d0);
                float a = av[tt];
                #pragma unroll
                for (int i = 0; i < 7; i++) {
                    float4 u = ur[i];
                    acc[4*i]   += a * u.x; acc[4*i+1] += a * u.y;
                    acc[4*i+2] += a * u.z; acc[4*i+3] += a * u.w;
                }
            }
            float* os = (float*)(sm + OFF_OS) + nl * 224;
            int base = (s4 >> 1) * 110 + (s4 & 1) * 5;
            #pragma unroll
            for (int dd = 0; dd < 28; dd++) {
                int d = d0 + dd;
                if (d < 55) {
                    int h = d / 5, w = d - (d / 5) * 5;
                    os[base + h * 10 + w] = acc[dd];
                }
            }
        }
        __syncthreads();

        // ======== store: coalesced OS -> gmem ========
        {
            float* gout = out + (size_t)t * 7040;
            const float* os = (const float*)(sm + OFF_OS);
            #pragma unroll
            for (int i = 0; i < 7; i++) {
                int idx = tid + 256 * i;
                if (idx < 1760) {
                    int n = idx / 55, jj = idx - n * 55;
                    *(float4*)(gout + n * 220 + jj * 4) =
                        *(const float4*)(os + n * 224 + jj * 4);
                }
            }
        }
    }
}

extern "C" void kernel_launch(void* const* d_in, const int* in_sizes, int n_in,
                              void* d_out, int out_size) {
    const float* x   = (const float*)d_in[0];
    const float* wq  = (const float*)d_in[1];
    const float* wk  = (const float*)d_in[2];
    const float* wv  = (const float*)d_in[3];
    const float* wfc = (const float*)d_in[4];
    const float* bfc = (const float*)d_in[5];
    float* out = (float*)d_out;

    int nsm = 148;
    cudaDeviceGetAttribute(&nsm, cudaDevAttrMultiProcessorCount, 0);

    cudaFuncSetAttribute(mha_kernel, cudaFuncAttributeMaxDynamicSharedMemorySize, SMEM_TOTAL);
    prep_kernel<<<(112 * 184 + 255) / 256, 256>>>(wq, wk, wv, wfc);
    mha_kernel<<<nsm, 256, SMEM_TOTAL>>>(x, bfc, out);
}